// round 13
// baseline (speedup 1.0000x reference)
#include <cuda_runtime.h>
#include <cuda_bf16.h>
#include <math_constants.h>

// NeighborsValuesAssigner: x(32,3,64,64), patches(2048,3,5,5), values(2048,128)
// out(32,128,64,64) fp32.
// dist = 0.5*||p||^2 - <p, window(x)>; top-8 smallest; out = mean values[idx].
//
// Pipeline:
//  1. prep:   bf16 patch matrix (negated, split bias, MMA-permuted) + fp32 table
//  2. gemm:   fused im2col + bf16 mma.sync, M=32 per warp, 128-thread blocks
//             at occupancy 4 (16 warps/SM for stall coverage); per-lane top-8
//             float keys (patch idx in low 11 mantissa bits), batch-4 sort +
//             bitonic merge -> 32 candidates/position
//  3. rescue: exact fp32 distance on 32 candidates -> true top-8 indices
//  4. gather: mean of values rows

#define BB 32
#define CC 3
#define HW 64
#define NN 2048
#define DD 128
#define KNN 8
#define KVOL 75
#define KM 80                 // K padded for k16 MMA tiles
#define KM32 (KM / 2)         // 40 u32 per bf16x2 row
#define NPOS (BB * HW * HW)   // 131072
#define LL 8                  // per-lane candidate list length
#define NCAND 32              // 4 lanes * LL per position
#define PFW 96                // padded fp32 patch row (8 lanes x 12 floats)

__device__ float g_bias[NN];
__device__ float g_pf[NN * PFW];               // padded fp32 patch rows
__device__ unsigned g_pBu[NN * KM32];          // bf16x2 patch matrix (permuted)
__device__ unsigned g_cand[NPOS * NCAND];      // packed candidate keys (16.8 MB)
__device__ int g_topk[NPOS * KNN];

// order-preserving float->u32 key (rescue only; exact ranking)
__device__ __forceinline__ unsigned okey(float f) {
    unsigned u = __float_as_uint(f);
    int s = ((int)u) >> 31;
    return u ^ (unsigned)(s | 0x80000000);
}

// GEMM key: distance float with low 11 mantissa bits replaced by patch index.
// One LOP3. FMNMX orders floats correctly incl. negatives; index-bit ties are
// resolved exactly by the rescue pass.
__device__ __forceinline__ float packkeyf(float c, unsigned pidx) {
    unsigned u = (__float_as_uint(c) & 0xFFFFF800u) | pidx;
    return __uint_as_float(u);
}

// float compare-exchange (FMNMX)
#define FCEV(arr, a, b) { float _lo = fminf(arr[a], arr[b]); \
                          arr[b] = fmaxf(arr[a], arr[b]); arr[a] = _lo; }

__device__ __forceinline__ void sort4f(float* v) {
    FCEV(v,0,1) FCEV(v,2,3)
    FCEV(v,0,2) FCEV(v,1,3)
    FCEV(v,1,2)
}
// L sorted asc(8), v sorted asc(4): L <- 8 smallest of union, sorted.
// min(asc-8, [inf,inf,inf,inf,v3..v0]) is bitonic -> 12-CE bitonic merger.
__device__ __forceinline__ void merge4f(float* L, float* v) {
    L[4] = fminf(L[4], v[3]);
    L[5] = fminf(L[5], v[2]);
    L[6] = fminf(L[6], v[1]);
    L[7] = fminf(L[7], v[0]);
    FCEV(L,0,4) FCEV(L,1,5) FCEV(L,2,6) FCEV(L,3,7)
    FCEV(L,0,2) FCEV(L,1,3) FCEV(L,4,6) FCEV(L,5,7)
    FCEV(L,0,1) FCEV(L,2,3) FCEV(L,4,5) FCEV(L,6,7)
}

// ---------------------------------------------------------------------------
// Kernel 1: prep — bias, padded fp32 rows, negated bf16 rows w/ split bias,
// written in the MMA-fragment permuted order so GEMM staging is a plain copy.
// ---------------------------------------------------------------------------
__global__ void prep_kernel(const float* __restrict__ patches) {
    int n = blockIdx.x * blockDim.x + threadIdx.x;
    if (n >= NN) return;
    const float* p = patches + n * KVOL;
    float s = 0.f;
    float pv[KM];
    float* pf = g_pf + n * PFW;
#pragma unroll
    for (int i = 0; i < KVOL; i++) {
        float v = p[i];
        s = fmaf(v, v, s);
        pv[i] = -v;
        pf[i] = v;
    }
#pragma unroll
    for (int i = KVOL; i < PFW; i++) pf[i] = 0.f;
    float bias = 0.5f * s;
    g_bias[n] = bias;
    float bh = __bfloat162float(__float2bfloat16_rn(bias));
    pv[75] = bh;
    pv[76] = bias - bh;
    pv[77] = 0.f; pv[78] = 0.f; pv[79] = 0.f;
    unsigned* dst = g_pBu + n * KM32;
#pragma unroll
    for (int k = 0; k < KM32; k++) {
        __nv_bfloat162 h2 = __floats2bfloat162_rn(pv[2 * k], pv[2 * k + 1]);
        int pp = (k & ~7) | ((k & 3) << 1) | ((k & 4) >> 2);
        dst[pp] = *reinterpret_cast<unsigned*>(&h2);
    }
}

// ---------------------------------------------------------------------------
// Kernel 2: fused im2col + bf16 mma.sync GEMM + batch-4 top-8 selection.
// 128 threads = 4 warps; warp owns 32 positions (two m16 A-tiles sharing every
// B fragment). Occupancy 4 -> 16 warps/SM.
// ---------------------------------------------------------------------------
__global__ void __launch_bounds__(128, 4)
gemm_topk_kernel(const float* __restrict__ x) {
    __shared__ float sX[CC][6][68];     // rows h0-2..h0+3, w -2..65 (zero-pad)
    __shared__ unsigned sB[128 * KM32]; // 20 KB

    int tid = threadIdx.x;
    int warp = tid >> 5;
    int lane = tid & 31;
    int pos0 = blockIdx.x * 128;
    int b = pos0 >> 12;
    int h0 = (pos0 >> 6) & 63;          // multiple of 2

    // ---- stage x tile (2 output rows + halo) ----
    for (int i = tid; i < CC * 6 * 68; i += 128) {
        int c = i / (6 * 68);
        int rem = i - c * 6 * 68;
        int r = rem / 68;
        int wi = rem - r * 68;
        int hy = h0 - 2 + r;
        int wx = wi - 2;
        float v = 0.f;
        if (hy >= 0 && hy < HW && wx >= 0 && wx < HW)
            v = x[((b * CC + c) * HW + hy) * HW + wx];
        sX[c][r][wi] = v;
    }
    __syncthreads();

    // warp -> h row (hh) + 32-wide w segment
    int hh = warp >> 1;                     // 0..1
    int wseg = (warp & 1) * 32;
    int w1 = wseg + (lane >> 2);            // tile rows at w1, +8, +16, +24
    int cq = lane & 3;
    int r1 = pos0 + hh * 64 + w1;           // global position of list 0

    // ---- A fragments: 5 k-tiles x (4 regs tile0 + 4 regs tile1) ----
    unsigned aR[5][8];
#pragma unroll
    for (int kt = 0; kt < 5; kt++) {
        int eb = 16 * kt + 2 * cq;
        float f[4][4]; // [w-offset 0/8/16/24][e0,e1,e2,e3]
#pragma unroll
        for (int t = 0; t < 4; t++) {
            int e = eb + (t >> 1) * 8 + (t & 1);
            if (e >= 77) {
#pragma unroll
                for (int o = 0; o < 4; o++) f[o][t] = 0.f;
            } else if (e >= 75) {
#pragma unroll
                for (int o = 0; o < 4; o++) f[o][t] = 1.f;
            } else {
                int c = e / 25;
                int r = (e % 25) / 5;
                int q = e % 5;
#pragma unroll
                for (int o = 0; o < 4; o++)
                    f[o][t] = sX[c][hh + r][w1 + o * 8 + q];
            }
        }
        __nv_bfloat162 h2;
        h2 = __floats2bfloat162_rn(f[0][0], f[0][1]); aR[kt][0] = *(unsigned*)&h2;
        h2 = __floats2bfloat162_rn(f[1][0], f[1][1]); aR[kt][1] = *(unsigned*)&h2;
        h2 = __floats2bfloat162_rn(f[0][2], f[0][3]); aR[kt][2] = *(unsigned*)&h2;
        h2 = __floats2bfloat162_rn(f[1][2], f[1][3]); aR[kt][3] = *(unsigned*)&h2;
        h2 = __floats2bfloat162_rn(f[2][0], f[2][1]); aR[kt][4] = *(unsigned*)&h2;
        h2 = __floats2bfloat162_rn(f[3][0], f[3][1]); aR[kt][5] = *(unsigned*)&h2;
        h2 = __floats2bfloat162_rn(f[2][2], f[2][3]); aR[kt][6] = *(unsigned*)&h2;
        h2 = __floats2bfloat162_rn(f[3][2], f[3][3]); aR[kt][7] = *(unsigned*)&h2;
    }

    float lv0[LL], lv1[LL], lv2[LL], lv3[LL];
#pragma unroll
    for (int j = 0; j < LL; j++) {
        lv0[j] = CUDART_INF_F; lv1[j] = CUDART_INF_F;
        lv2[j] = CUDART_INF_F; lv3[j] = CUDART_INF_F;
    }

    for (int ch = 0; ch < 16; ch++) {
        __syncthreads();
        // straight vectorized copy: layout already MMA-permuted
        const uint4* src4 = reinterpret_cast<const uint4*>(g_pBu + ch * 128 * KM32);
        uint4* dst4 = reinterpret_cast<uint4*>(sB);
#pragma unroll
        for (int t = 0; t < 10; t++)
            dst4[tid + t * 128] = src4[tid + t * 128];
        __syncthreads();

#pragma unroll
        for (int np = 0; np < 8; np++) {   // nt pairs
            float v0[4], v1[4], v2[4], v3[4];
#pragma unroll
            for (int t = 0; t < 2; t++) {
                int nt = np * 2 + t;
                const uint2* bp = reinterpret_cast<const uint2*>(
                    sB + (nt * 8 + (lane >> 2)) * KM32) + cq;
                float c0 = 0.f, c1 = 0.f, c2 = 0.f, c3 = 0.f;
                float d0 = 0.f, d1 = 0.f, d2 = 0.f, d3 = 0.f;
#pragma unroll
                for (int kt = 0; kt < 5; kt++) {
                    uint2 bb = bp[kt * 4]; // one LDS.64, feeds both MMAs
                    asm volatile(
                        "mma.sync.aligned.m16n8k16.row.col.f32.bf16.bf16.f32 "
                        "{%0,%1,%2,%3}, {%4,%5,%6,%7}, {%8,%9}, {%0,%1,%2,%3};"
                        : "+f"(c0), "+f"(c1), "+f"(c2), "+f"(c3)
                        : "r"(aR[kt][0]), "r"(aR[kt][1]), "r"(aR[kt][2]), "r"(aR[kt][3]),
                          "r"(bb.x), "r"(bb.y));
                    asm volatile(
                        "mma.sync.aligned.m16n8k16.row.col.f32.bf16.bf16.f32 "
                        "{%0,%1,%2,%3}, {%4,%5,%6,%7}, {%8,%9}, {%0,%1,%2,%3};"
                        : "+f"(d0), "+f"(d1), "+f"(d2), "+f"(d3)
                        : "r"(aR[kt][4]), "r"(aR[kt][5]), "r"(aR[kt][6]), "r"(aR[kt][7]),
                          "r"(bb.x), "r"(bb.y));
                }
                unsigned pidx = ch * 128 + nt * 8 + cq * 2;
                v0[2 * t] = packkeyf(c0, pidx); v0[2 * t + 1] = packkeyf(c1, pidx + 1);
                v1[2 * t] = packkeyf(c2, pidx); v1[2 * t + 1] = packkeyf(c3, pidx + 1);
                v2[2 * t] = packkeyf(d0, pidx); v2[2 * t + 1] = packkeyf(d1, pidx + 1);
                v3[2 * t] = packkeyf(d2, pidx); v3[2 * t + 1] = packkeyf(d3, pidx + 1);
            }
            sort4f(v0); merge4f(lv0, v0);
            sort4f(v1); merge4f(lv1, v1);
            sort4f(v2); merge4f(lv2, v2);
            sort4f(v3); merge4f(lv3, v3);
        }
    }

    unsigned* c0p = g_cand + (size_t)r1 * NCAND + cq * LL;
    unsigned* c1p = g_cand + (size_t)(r1 + 8) * NCAND + cq * LL;
    unsigned* c2p = g_cand + (size_t)(r1 + 16) * NCAND + cq * LL;
    unsigned* c3p = g_cand + (size_t)(r1 + 24) * NCAND + cq * LL;
#pragma unroll
    for (int j = 0; j < LL; j++) {
        c0p[j] = __float_as_uint(lv0[j]);
        c1p[j] = __float_as_uint(lv1[j]);
        c2p[j] = __float_as_uint(lv2[j]);
        c3p[j] = __float_as_uint(lv3[j]);
    }
}

// ---------------------------------------------------------------------------
// Kernel 3: exact fp32 rescue — warp per position, 4 groups of 8 lanes,
// 8 candidates per group, 3-shfl group reduce, min-extract top-8 of 32.
// (Reads only the low 11 index bits of each candidate key.)
// ---------------------------------------------------------------------------
__global__ void __launch_bounds__(256)
rescue_kernel(const float* __restrict__ x) {
    int warp = threadIdx.x >> 5;
    int lane = threadIdx.x & 31;
    int grp = lane >> 3;      // 0..3
    int sub = lane & 7;       // 0..7
    int pos = blockIdx.x * 8 + warp;
    int w = pos & 63;
    int h = (pos >> 6) & 63;
    int b = pos >> 12;

    float xw[12];
#pragma unroll
    for (int t = 0; t < 12; t++) {
        int e = sub * 12 + t;
        float v = 0.f;
        if (e < KVOL) {
            int c = e / 25;
            int r = (e % 25) / 5;
            int q = e % 5;
            int hy = h + r - 2;
            int wx = w + q - 2;
            if (hy >= 0 && hy < HW && wx >= 0 && wx < HW)
                v = x[((b * CC + c) * HW + hy) * HW + wx];
        }
        xw[t] = v;
    }

    const unsigned* cp = g_cand + (size_t)pos * NCAND;
    unsigned cA = cp[grp * 8 + sub];

    unsigned k1 = 0xFFFFFFFFu;
    int i1 = 0;
    const float4* pf = reinterpret_cast<const float4*>(g_pf);

#pragma unroll
    for (int c = 0; c < 8; c++) {
        unsigned kraw = __shfl_sync(0xffffffffu, cA, grp * 8 + c);
        int idx = (int)(kraw & 0x7FFu);
        const float4* row = pf + idx * (PFW / 4) + sub * 3;
        float4 a = row[0], bq = row[1], cc = row[2];
        float s;
        s = fmaf(a.x,  xw[0],  a.y * xw[1]);
        s = fmaf(a.z,  xw[2],  s);
        s = fmaf(a.w,  xw[3],  s);
        s = fmaf(bq.x, xw[4],  s);
        s = fmaf(bq.y, xw[5],  s);
        s = fmaf(bq.z, xw[6],  s);
        s = fmaf(bq.w, xw[7],  s);
        s = fmaf(cc.x, xw[8],  s);
        s = fmaf(cc.y, xw[9],  s);
        s = fmaf(cc.z, xw[10], s);
        s = fmaf(cc.w, xw[11], s);
        s += __shfl_xor_sync(0xffffffffu, s, 4);
        s += __shfl_xor_sync(0xffffffffu, s, 2);
        s += __shfl_xor_sync(0xffffffffu, s, 1);
        float dist = g_bias[idx] - s;
        if (sub == c) { k1 = okey(dist); i1 = idx; }
    }

    int* outp = g_topk + (size_t)pos * KNN;
#pragma unroll
    for (int it = 0; it < KNN; it++) {
        unsigned m = __reduce_min_sync(0xffffffffu, k1);
        bool own = (k1 == m);
        unsigned bal = __ballot_sync(0xffffffffu, own);
        int leader = __ffs(bal) - 1;
        if (lane == leader) {
            outp[it] = i1;
            k1 = 0xFFFFFFFFu;
        }
    }
}

// ---------------------------------------------------------------------------
// Kernel 4: gather + mean (coalesced via smem transpose).
// ---------------------------------------------------------------------------
__global__ void __launch_bounds__(256)
gather_kernel(const float* __restrict__ values, float* __restrict__ out) {
    __shared__ float ssum[32][133];

    int bh = blockIdx.x;
    int wt = blockIdx.y;
    int b = bh >> 6;
    int h = bh & 63;
    int w0 = wt * 32;

    int warp = threadIdx.x >> 5;
    int lane = threadIdx.x & 31;
    const float4* v4 = reinterpret_cast<const float4*>(values);

#pragma unroll
    for (int r = 0; r < 4; r++) {
        int pl = warp + r * 8;
        int pos = (bh * HW) + w0 + pl;
        const int* ip = g_topk + (size_t)pos * KNN;
        float4 a = make_float4(0.f, 0.f, 0.f, 0.f);
#pragma unroll
        for (int k = 0; k < KNN; k++) {
            int idx = ip[k];
            float4 v = v4[idx * (DD / 4) + lane];
            a.x += v.x; a.y += v.y; a.z += v.z; a.w += v.w;
        }
        ssum[pl][lane * 4 + 0] = a.x * 0.125f;
        ssum[pl][lane * 4 + 1] = a.y * 0.125f;
        ssum[pl][lane * 4 + 2] = a.z * 0.125f;
        ssum[pl][lane * 4 + 3] = a.w * 0.125f;
    }
    __syncthreads();

    int wl = threadIdx.x & 31;
    int d0 = threadIdx.x >> 5;
#pragma unroll
    for (int d = d0; d < DD; d += 8) {
        out[((b * DD + d) * HW + h) * HW + w0 + wl] = ssum[wl][d];
    }
}

// ---------------------------------------------------------------------------
extern "C" void kernel_launch(void* const* d_in, const int* in_sizes, int n_in,
                              void* d_out, int out_size) {
    const float* x = (const float*)d_in[0];
    const float* patches = (const float*)d_in[1];
    const float* values = (const float*)d_in[2];
    float* out = (float*)d_out;

    prep_kernel<<<(NN + 127) / 128, 128>>>(patches);
    gemm_topk_kernel<<<NPOS / 128, 128>>>(x);
    rescue_kernel<<<NPOS / 8, 256>>>(x);
    gather_kernel<<<dim3(BB * HW, 2), 256>>>(values, out);
}

// round 14
// speedup vs baseline: 1.0223x; 1.0223x over previous
#include <cuda_runtime.h>
#include <cuda_bf16.h>
#include <math_constants.h>

// NeighborsValuesAssigner: x(32,3,64,64), patches(2048,3,5,5), values(2048,128)
// out(32,128,64,64) fp32.
// dist = 0.5*||p||^2 - <p, window(x)>; top-8 smallest; out = mean values[idx].
//
// Pipeline:
//  1. prep:   bf16 patch matrix (negated, split bias, MMA-permuted) + fp32 table
//  2. gemm:   fused im2col + bf16 mma.sync, M=32 per warp (round-10 best);
//             per-lane top-8 float keys, batched sort8 + bitonic merge ->
//             32 candidates/position
//  3. rescue: exact fp32 distance on 32 candidates; candidate rows read as
//             CONTIGUOUS 128B per 8-lane group per instruction (1 line/group,
//             3x fewer L1 wavefronts than strided layout)
//  4. gather: mean of values rows

#define BB 32
#define CC 3
#define HW 64
#define NN 2048
#define DD 128
#define KNN 8
#define KVOL 75
#define KM 80                 // K padded for k16 MMA tiles
#define KM32 (KM / 2)         // 40 u32 per bf16x2 row
#define NPOS (BB * HW * HW)   // 131072
#define LL 8                  // per-lane candidate list length
#define NCAND 32              // 4 lanes * LL per position
#define PFW 96                // padded fp32 patch row (8 lanes x 12 floats)

__device__ float g_bias[NN];
__device__ float g_pf[NN * PFW];               // padded fp32 patch rows
__device__ unsigned g_pBu[NN * KM32];          // bf16x2 patch matrix (permuted)
__device__ unsigned g_cand[NPOS * NCAND];      // packed candidate keys (16.8 MB)
__device__ int g_topk[NPOS * KNN];

// order-preserving float->u32 key (rescue only; exact ranking)
__device__ __forceinline__ unsigned okey(float f) {
    unsigned u = __float_as_uint(f);
    int s = ((int)u) >> 31;
    return u ^ (unsigned)(s | 0x80000000);
}

// GEMM key: distance float with low 11 mantissa bits replaced by patch index.
// One LOP3. FMNMX orders floats correctly incl. negatives; index-bit ties are
// resolved exactly by the rescue pass.
__device__ __forceinline__ float packkeyf(float c, unsigned pidx) {
    unsigned u = (__float_as_uint(c) & 0xFFFFF800u) | pidx;
    return __uint_as_float(u);
}

// float compare-exchange (FMNMX)
#define FCEV(arr, a, b) { float _lo = fminf(arr[a], arr[b]); \
                          arr[b] = fmaxf(arr[a], arr[b]); arr[a] = _lo; }

__device__ __forceinline__ void sort8f(float* v) {
    FCEV(v,0,1) FCEV(v,2,3) FCEV(v,4,5) FCEV(v,6,7)
    FCEV(v,0,2) FCEV(v,1,3) FCEV(v,4,6) FCEV(v,5,7)
    FCEV(v,1,2) FCEV(v,5,6) FCEV(v,0,4) FCEV(v,3,7)
    FCEV(v,1,5) FCEV(v,2,6)
    FCEV(v,1,4) FCEV(v,3,6)
    FCEV(v,2,4) FCEV(v,3,5)
    FCEV(v,3,4)
}
// L sorted asc(8), v sorted asc(8): L <- 8 smallest of union, sorted.
__device__ __forceinline__ void merge8f(float* L, float* v) {
#pragma unroll
    for (int j = 0; j < LL; j++) L[j] = fminf(L[j], v[7 - j]);
    FCEV(L,0,4) FCEV(L,1,5) FCEV(L,2,6) FCEV(L,3,7)
    FCEV(L,0,2) FCEV(L,1,3) FCEV(L,4,6) FCEV(L,5,7)
    FCEV(L,0,1) FCEV(L,2,3) FCEV(L,4,5) FCEV(L,6,7)
}

// ---------------------------------------------------------------------------
// Kernel 1: prep — bias, padded fp32 rows, negated bf16 rows w/ split bias,
// written in the MMA-fragment permuted order so GEMM staging is a plain copy.
// ---------------------------------------------------------------------------
__global__ void prep_kernel(const float* __restrict__ patches) {
    int n = blockIdx.x * blockDim.x + threadIdx.x;
    if (n >= NN) return;
    const float* p = patches + n * KVOL;
    float s = 0.f;
    float pv[KM];
    float* pf = g_pf + n * PFW;
#pragma unroll
    for (int i = 0; i < KVOL; i++) {
        float v = p[i];
        s = fmaf(v, v, s);
        pv[i] = -v;
        pf[i] = v;
    }
#pragma unroll
    for (int i = KVOL; i < PFW; i++) pf[i] = 0.f;
    float bias = 0.5f * s;
    g_bias[n] = bias;
    float bh = __bfloat162float(__float2bfloat16_rn(bias));
    pv[75] = bh;
    pv[76] = bias - bh;
    pv[77] = 0.f; pv[78] = 0.f; pv[79] = 0.f;
    unsigned* dst = g_pBu + n * KM32;
#pragma unroll
    for (int k = 0; k < KM32; k++) {
        __nv_bfloat162 h2 = __floats2bfloat162_rn(pv[2 * k], pv[2 * k + 1]);
        int pp = (k & ~7) | ((k & 3) << 1) | ((k & 4) >> 2);
        dst[pp] = *reinterpret_cast<unsigned*>(&h2);
    }
}

// ---------------------------------------------------------------------------
// Kernel 2: fused im2col + bf16 mma.sync GEMM + batched top-8 selection.
// (round-10 best-measured configuration, unchanged)
// ---------------------------------------------------------------------------
__global__ void __launch_bounds__(128, 3)
gemm_topk_kernel(const float* __restrict__ x) {
    __shared__ float sX[CC][6][68];     // rows h0-2..h0+3, w -2..65 (zero-pad)
    __shared__ unsigned sB[128 * KM32]; // 20 KB

    int tid = threadIdx.x;
    int warp = tid >> 5;
    int lane = tid & 31;
    int pos0 = blockIdx.x * 128;
    int b = pos0 >> 12;
    int h0 = (pos0 >> 6) & 63;          // multiple of 2

    // ---- stage x tile (2 output rows + halo) ----
    for (int i = tid; i < CC * 6 * 68; i += 128) {
        int c = i / (6 * 68);
        int rem = i - c * 6 * 68;
        int r = rem / 68;
        int wi = rem - r * 68;
        int hy = h0 - 2 + r;
        int wx = wi - 2;
        float v = 0.f;
        if (hy >= 0 && hy < HW && wx >= 0 && wx < HW)
            v = x[((b * CC + c) * HW + hy) * HW + wx];
        sX[c][r][wi] = v;
    }
    __syncthreads();

    // warp -> h row (hh) + 32-wide w segment
    int hh = warp >> 1;                     // 0..1
    int wseg = (warp & 1) * 32;
    int w1 = wseg + (lane >> 2);            // tile rows at w1, +8, +16, +24
    int cq = lane & 3;
    int r1 = pos0 + hh * 64 + w1;           // global position of list 0

    // ---- A fragments: 5 k-tiles x (4 regs tile0 + 4 regs tile1) ----
    unsigned aR[5][8];
#pragma unroll
    for (int kt = 0; kt < 5; kt++) {
        int eb = 16 * kt + 2 * cq;
        float f[4][4]; // [w-offset 0/8/16/24][e0,e1,e2,e3]
#pragma unroll
        for (int t = 0; t < 4; t++) {
            int e = eb + (t >> 1) * 8 + (t & 1);
            if (e >= 77) {
#pragma unroll
                for (int o = 0; o < 4; o++) f[o][t] = 0.f;
            } else if (e >= 75) {
#pragma unroll
                for (int o = 0; o < 4; o++) f[o][t] = 1.f;
            } else {
                int c = e / 25;
                int r = (e % 25) / 5;
                int q = e % 5;
#pragma unroll
                for (int o = 0; o < 4; o++)
                    f[o][t] = sX[c][hh + r][w1 + o * 8 + q];
            }
        }
        __nv_bfloat162 h2;
        h2 = __floats2bfloat162_rn(f[0][0], f[0][1]); aR[kt][0] = *(unsigned*)&h2;
        h2 = __floats2bfloat162_rn(f[1][0], f[1][1]); aR[kt][1] = *(unsigned*)&h2;
        h2 = __floats2bfloat162_rn(f[0][2], f[0][3]); aR[kt][2] = *(unsigned*)&h2;
        h2 = __floats2bfloat162_rn(f[1][2], f[1][3]); aR[kt][3] = *(unsigned*)&h2;
        h2 = __floats2bfloat162_rn(f[2][0], f[2][1]); aR[kt][4] = *(unsigned*)&h2;
        h2 = __floats2bfloat162_rn(f[3][0], f[3][1]); aR[kt][5] = *(unsigned*)&h2;
        h2 = __floats2bfloat162_rn(f[2][2], f[2][3]); aR[kt][6] = *(unsigned*)&h2;
        h2 = __floats2bfloat162_rn(f[3][2], f[3][3]); aR[kt][7] = *(unsigned*)&h2;
    }

    float lv0[LL], lv1[LL], lv2[LL], lv3[LL];
#pragma unroll
    for (int j = 0; j < LL; j++) {
        lv0[j] = CUDART_INF_F; lv1[j] = CUDART_INF_F;
        lv2[j] = CUDART_INF_F; lv3[j] = CUDART_INF_F;
    }

    for (int ch = 0; ch < 16; ch++) {
        __syncthreads();
        // straight vectorized copy: layout already MMA-permuted
        const uint4* src4 = reinterpret_cast<const uint4*>(g_pBu + ch * 128 * KM32);
        uint4* dst4 = reinterpret_cast<uint4*>(sB);
#pragma unroll
        for (int t = 0; t < 10; t++)
            dst4[tid + t * 128] = src4[tid + t * 128];
        __syncthreads();

#pragma unroll
        for (int ntg = 0; ntg < 4; ntg++) {
            float v0[8], v1[8], v2[8], v3[8];
#pragma unroll
            for (int t = 0; t < 4; t++) {
                int nt = ntg * 4 + t;
                const uint2* bp = reinterpret_cast<const uint2*>(
                    sB + (nt * 8 + (lane >> 2)) * KM32) + cq;
                float c0 = 0.f, c1 = 0.f, c2 = 0.f, c3 = 0.f;
                float d0 = 0.f, d1 = 0.f, d2 = 0.f, d3 = 0.f;
#pragma unroll
                for (int kt = 0; kt < 5; kt++) {
                    uint2 bb = bp[kt * 4]; // one LDS.64, feeds both MMAs
                    asm volatile(
                        "mma.sync.aligned.m16n8k16.row.col.f32.bf16.bf16.f32 "
                        "{%0,%1,%2,%3}, {%4,%5,%6,%7}, {%8,%9}, {%0,%1,%2,%3};"
                        : "+f"(c0), "+f"(c1), "+f"(c2), "+f"(c3)
                        : "r"(aR[kt][0]), "r"(aR[kt][1]), "r"(aR[kt][2]), "r"(aR[kt][3]),
                          "r"(bb.x), "r"(bb.y));
                    asm volatile(
                        "mma.sync.aligned.m16n8k16.row.col.f32.bf16.bf16.f32 "
                        "{%0,%1,%2,%3}, {%4,%5,%6,%7}, {%8,%9}, {%0,%1,%2,%3};"
                        : "+f"(d0), "+f"(d1), "+f"(d2), "+f"(d3)
                        : "r"(aR[kt][4]), "r"(aR[kt][5]), "r"(aR[kt][6]), "r"(aR[kt][7]),
                          "r"(bb.x), "r"(bb.y));
                }
                unsigned pidx = ch * 128 + nt * 8 + cq * 2;
                v0[2 * t] = packkeyf(c0, pidx); v0[2 * t + 1] = packkeyf(c1, pidx + 1);
                v1[2 * t] = packkeyf(c2, pidx); v1[2 * t + 1] = packkeyf(c3, pidx + 1);
                v2[2 * t] = packkeyf(d0, pidx); v2[2 * t + 1] = packkeyf(d1, pidx + 1);
                v3[2 * t] = packkeyf(d2, pidx); v3[2 * t + 1] = packkeyf(d3, pidx + 1);
            }
            sort8f(v0); merge8f(lv0, v0);
            sort8f(v1); merge8f(lv1, v1);
            sort8f(v2); merge8f(lv2, v2);
            sort8f(v3); merge8f(lv3, v3);
        }
    }

    unsigned* c0p = g_cand + (size_t)r1 * NCAND + cq * LL;
    unsigned* c1p = g_cand + (size_t)(r1 + 8) * NCAND + cq * LL;
    unsigned* c2p = g_cand + (size_t)(r1 + 16) * NCAND + cq * LL;
    unsigned* c3p = g_cand + (size_t)(r1 + 24) * NCAND + cq * LL;
#pragma unroll
    for (int j = 0; j < LL; j++) {
        c0p[j] = __float_as_uint(lv0[j]);
        c1p[j] = __float_as_uint(lv1[j]);
        c2p[j] = __float_as_uint(lv2[j]);
        c3p[j] = __float_as_uint(lv3[j]);
    }
}

// ---------------------------------------------------------------------------
// Kernel 3: exact fp32 rescue — warp per position, 4 groups of 8 lanes.
// CONTIGUOUS layout: in instruction t, group lane sub loads float4 (sub + 8t)
// of the row -> 128B = exactly 1 cache line per group per instruction
// (12 wavefronts per candidate-iter instead of 36). Lane sub therefore owns
// window elements {32t + 4*sub + u} for t=0..2, u=0..3.
// ---------------------------------------------------------------------------
__global__ void __launch_bounds__(256)
rescue_kernel(const float* __restrict__ x) {
    int warp = threadIdx.x >> 5;
    int lane = threadIdx.x & 31;
    int grp = lane >> 3;      // 0..3
    int sub = lane & 7;       // 0..7
    int pos = blockIdx.x * 8 + warp;
    int w = pos & 63;
    int h = (pos >> 6) & 63;
    int b = pos >> 12;

    // xw[t*4+u] = window element (32t + 4*sub + u), zero beyond KVOL
    float xw[12];
#pragma unroll
    for (int t = 0; t < 3; t++) {
#pragma unroll
        for (int u = 0; u < 4; u++) {
            int e = 32 * t + 4 * sub + u;
            float v = 0.f;
            if (e < KVOL) {
                int c = e / 25;
                int r = (e % 25) / 5;
                int q = e % 5;
                int hy = h + r - 2;
                int wx = w + q - 2;
                if (hy >= 0 && hy < HW && wx >= 0 && wx < HW)
                    v = x[((b * CC + c) * HW + hy) * HW + wx];
            }
            xw[t * 4 + u] = v;
        }
    }

    // group g owns candidates 8g..8g+7; lane sub holds candidate sub
    const unsigned* cp = g_cand + (size_t)pos * NCAND;
    unsigned cA = cp[grp * 8 + sub];

    unsigned k1 = 0xFFFFFFFFu;
    int i1 = 0;
    const float4* pf = reinterpret_cast<const float4*>(g_pf);

#pragma unroll
    for (int c = 0; c < 8; c++) {
        unsigned kraw = __shfl_sync(0xffffffffu, cA, grp * 8 + c);
        int idx = (int)(kraw & 0x7FFu);
        const float4* row = pf + idx * (PFW / 4) + sub;
        float4 a  = row[0];   // float4 index sub      -> elems 4sub..4sub+3
        float4 bq = row[8];   // float4 index sub+8    -> elems 32+4sub..
        float4 cc = row[16];  // float4 index sub+16   -> elems 64+4sub..
        float s;
        s = fmaf(a.x,  xw[0],  a.y * xw[1]);
        s = fmaf(a.z,  xw[2],  s);
        s = fmaf(a.w,  xw[3],  s);
        s = fmaf(bq.x, xw[4],  s);
        s = fmaf(bq.y, xw[5],  s);
        s = fmaf(bq.z, xw[6],  s);
        s = fmaf(bq.w, xw[7],  s);
        s = fmaf(cc.x, xw[8],  s);
        s = fmaf(cc.y, xw[9],  s);
        s = fmaf(cc.z, xw[10], s);
        s = fmaf(cc.w, xw[11], s);
        // reduce within the 8-lane group (warp-wide shfl serves all 4 groups)
        s += __shfl_xor_sync(0xffffffffu, s, 4);
        s += __shfl_xor_sync(0xffffffffu, s, 2);
        s += __shfl_xor_sync(0xffffffffu, s, 1);
        float dist = g_bias[idx] - s;
        if (sub == c) { k1 = okey(dist); i1 = idx; }
    }

    int* outp = g_topk + (size_t)pos * KNN;
#pragma unroll
    for (int it = 0; it < KNN; it++) {
        unsigned m = __reduce_min_sync(0xffffffffu, k1);
        bool own = (k1 == m);
        unsigned bal = __ballot_sync(0xffffffffu, own);
        int leader = __ffs(bal) - 1;
        if (lane == leader) {
            outp[it] = i1;
            k1 = 0xFFFFFFFFu;
        }
    }
}

// ---------------------------------------------------------------------------
// Kernel 4: gather + mean (coalesced via smem transpose).
// ---------------------------------------------------------------------------
__global__ void __launch_bounds__(256)
gather_kernel(const float* __restrict__ values, float* __restrict__ out) {
    __shared__ float ssum[32][133];

    int bh = blockIdx.x;
    int wt = blockIdx.y;
    int b = bh >> 6;
    int h = bh & 63;
    int w0 = wt * 32;

    int warp = threadIdx.x >> 5;
    int lane = threadIdx.x & 31;
    const float4* v4 = reinterpret_cast<const float4*>(values);

#pragma unroll
    for (int r = 0; r < 4; r++) {
        int pl = warp + r * 8;
        int pos = (bh * HW) + w0 + pl;
        const int* ip = g_topk + (size_t)pos * KNN;
        float4 a = make_float4(0.f, 0.f, 0.f, 0.f);
#pragma unroll
        for (int k = 0; k < KNN; k++) {
            int idx = ip[k];
            float4 v = v4[idx * (DD / 4) + lane];
            a.x += v.x; a.y += v.y; a.z += v.z; a.w += v.w;
        }
        ssum[pl][lane * 4 + 0] = a.x * 0.125f;
        ssum[pl][lane * 4 + 1] = a.y * 0.125f;
        ssum[pl][lane * 4 + 2] = a.z * 0.125f;
        ssum[pl][lane * 4 + 3] = a.w * 0.125f;
    }
    __syncthreads();

    int wl = threadIdx.x & 31;
    int d0 = threadIdx.x >> 5;
#pragma unroll
    for (int d = d0; d < DD; d += 8) {
        out[((b * DD + d) * HW + h) * HW + w0 + wl] = ssum[wl][d];
    }
}

// ---------------------------------------------------------------------------
extern "C" void kernel_launch(void* const* d_in, const int* in_sizes, int n_in,
                              void* d_out, int out_size) {
    const float* x = (const float*)d_in[0];
    const float* patches = (const float*)d_in[1];
    const float* values = (const float*)d_in[2];
    float* out = (float*)d_out;

    prep_kernel<<<(NN + 127) / 128, 128>>>(patches);
    gemm_topk_kernel<<<NPOS / 128, 128>>>(x);
    rescue_kernel<<<NPOS / 8, 256>>>(x);
    gather_kernel<<<dim3(BB * HW, 2), 256>>>(values, out);
}